// round 6
// baseline (speedup 1.0000x reference)
#include <cuda_runtime.h>

// upfirdn2d(up=2, down=1, pad=5), 12x12 separable K = h h^T, via fma.rn.f32x2.
// Horizontal pass: (even,odd)-parity output pairs, broadcast input.
// Vertical pass: column-pair vectorization -> FFMA2 input is an aligned LDS.64
// of adjacent tmp columns; coefficients are broadcast pairs packed once.
// R5 fix: out image stride 511*511 is ODD -> STG.64 only for even img
// (element-offset parity is uniform per block), scalar stores otherwise.

#define IMG_H 256
#define IMG_W 256
#define OUT_H 511
#define OUT_W 511
#define TILE  64
#define IN_T  37      // input rows/cols needed per 64-wide output tile
#define SPITCH 38     // even pitch -> STS.64-aligned stores
#define TP2   33      // float2 pitch for tmp rows (66 floats)

__device__ __forceinline__ float2 ffma2(float2 a, float2 b, float2 c) {
    float2 d;
    asm("fma.rn.f32x2 %0, %1, %2, %3;"
        : "=l"(*reinterpret_cast<unsigned long long*>(&d))
        : "l"(*reinterpret_cast<unsigned long long*>(&a)),
          "l"(*reinterpret_cast<unsigned long long*>(&b)),
          "l"(*reinterpret_cast<unsigned long long*>(&c)));
    return d;
}

__device__ __forceinline__ float2 fmul2(float2 a, float2 b) {
    float2 d;
    asm("mul.rn.f32x2 %0, %1, %2;"
        : "=l"(*reinterpret_cast<unsigned long long*>(&d))
        : "l"(*reinterpret_cast<unsigned long long*>(&a)),
          "l"(*reinterpret_cast<unsigned long long*>(&b)));
    return d;
}

__device__ __forceinline__ float2 bcast(float w) { return make_float2(w, w); }

__global__ __launch_bounds__(256)
void lpf_up2_kernel(const float* __restrict__ x,
                    const float* __restrict__ K,
                    float* __restrict__ out) {
    __shared__ float  s_in[IN_T * SPITCH];   // input tile (zero-padded halo)
    __shared__ float2 s_tmp[IN_T * TP2];     // horiz result: 37 rows x 64 cols
    __shared__ float2 s_c[6];                // (he[t], ho[t]) interleaved
    __shared__ float2 s_ce[6];               // (he[t], he[t]) broadcast
    __shared__ float2 s_co[6];               // (ho[t], ho[t]) broadcast

    const int tid = threadIdx.x;
    const int img = blockIdx.z;
    const int ox0 = blockIdx.x * TILE;       // even
    const int oy0 = blockIdx.y * TILE;       // even
    const int mx0 = (ox0 >> 1) - 2;          // even
    const int my0 = (oy0 >> 1) - 2;

    // Recover separable h from K row 5: h[j] = K[5][j] / sqrt(K[5][5]).
    if (tid < 6) {
        float s  = rsqrtf(K[5 * 12 + 5]);
        float he = K[5 * 12 + (10 - 2 * tid)] * s;
        float ho = K[5 * 12 + (11 - 2 * tid)] * s;
        s_c[tid]  = make_float2(he, ho);
        s_ce[tid] = make_float2(he, he);
        s_co[tid] = make_float2(ho, ho);
    }

    // ---- Load input tile ----
    const float* __restrict__ xin = x + (size_t)img * (IMG_H * IMG_W);
    const bool interior =
        (mx0 >= 0) && (mx0 + 37 < IMG_W) && (my0 >= 0) && (my0 + 36 < IMG_H);

    if (interior) {
        // float2 path: 37 rows x 19 float2 (cols 0..37; col 37 is harmless pad).
        int r = tid / 19, c = tid - (tid / 19) * 19;
        #pragma unroll
        for (int it = 0; it < 3; it++) {
            if (r < IN_T) {
                float2 v = *reinterpret_cast<const float2*>(
                    xin + (my0 + r) * IMG_W + mx0 + 2 * c);
                *reinterpret_cast<float2*>(s_in + r * SPITCH + 2 * c) = v;
            }
            r += 13; c += 9;
            if (c >= 19) { c -= 19; r += 1; }
        }
    } else {
        int r = tid / IN_T, c = tid - (tid / IN_T) * IN_T;
        #pragma unroll
        for (int it = 0; it < 6; it++) {
            if (r < IN_T) {
                int gy = my0 + r, gx = mx0 + c;
                float v = 0.0f;
                if ((unsigned)gy < IMG_H && (unsigned)gx < IMG_W)
                    v = xin[gy * IMG_W + gx];
                s_in[r * SPITCH + c] = v;
            }
            r += 6; c += 34;
            if (c >= IN_T) { c -= IN_T; r += 1; }
        }
    }
    __syncthreads();

    // ---- Horizontal pass: tmp[r][pair k] = sum_t (he,ho)[t] * s_in[r][k+t] ----
    if (tid < IN_T * 4) {
        const float2 c0 = s_c[0], c1 = s_c[1], c2 = s_c[2],
                     c3 = s_c[3], c4 = s_c[4], c5 = s_c[5];
        int kg = tid / IN_T;            // 0..3
        int r  = tid - kg * IN_T;       // 0..36
        int k0 = kg * 8;
        const float* row = s_in + r * SPITCH;
        float2* trow = s_tmp + r * TP2;
        float2 p0 = bcast(row[k0 + 0]), p1 = bcast(row[k0 + 1]),
               p2 = bcast(row[k0 + 2]), p3 = bcast(row[k0 + 3]),
               p4 = bcast(row[k0 + 4]), p5 = bcast(row[k0 + 5]);
        #pragma unroll
        for (int j = 0; j < 8; j++) {
            float2 acc = fmul2(p0, c0);
            acc = ffma2(p1, c1, acc);
            acc = ffma2(p2, c2, acc);
            acc = ffma2(p3, c3, acc);
            acc = ffma2(p4, c4, acc);
            acc = ffma2(p5, c5, acc);
            trow[k0 + j] = acc;
            p0 = p1; p1 = p2; p2 = p3; p3 = p4; p4 = p5;
            if (j < 7) p5 = bcast(row[k0 + j + 6]);   // max col = 36
        }
    }
    __syncthreads();

    // ---- Vertical pass: column-pair vectorized ----
    // Thread = (colpair cp, rowgroup rg). ox = 2*cp; row-pairs J = rg*4..rg*4+3.
    {
        const int cp = tid & 31;        // 0..31
        const int rg = tid >> 5;        // 0..7
        const int ox = 2 * cp;
        const float* tf = reinterpret_cast<const float*>(s_tmp);  // row stride 66

        float2 ce0 = s_ce[0], ce1 = s_ce[1], ce2 = s_ce[2],
               ce3 = s_ce[3], ce4 = s_ce[4], ce5 = s_ce[5];
        float2 co0 = s_co[0], co1 = s_co[1], co2 = s_co[2],
               co3 = s_co[3], co4 = s_co[4], co5 = s_co[5];

        // Window of 9 tmp-rows, each an aligned float2 of adjacent columns.
        float2 W[9];
        #pragma unroll
        for (int i = 0; i < 9; i++)
            W[i] = *reinterpret_cast<const float2*>(tf + (rg * 4 + i) * (TP2 * 2) + ox);

        float* __restrict__ o_img = out + (size_t)img * ((size_t)OUT_H * OUT_W);
        const int  gox  = ox0 + ox;                 // even, <= 510
        const bool x2ok = (gox + 1 < OUT_W);        // false only at gox==510
        // 511*511 is odd -> element offset parity is (img & 1); goy*511, gox even.
        const bool al8  = ((img & 1) == 0);

        #pragma unroll
        for (int j = 0; j < 4; j++) {
            float2 ae = fmul2(W[j + 0], ce0);
            ae = ffma2(W[j + 1], ce1, ae);
            ae = ffma2(W[j + 2], ce2, ae);
            ae = ffma2(W[j + 3], ce3, ae);
            ae = ffma2(W[j + 4], ce4, ae);
            ae = ffma2(W[j + 5], ce5, ae);
            float2 ao = fmul2(W[j + 0], co0);
            ao = ffma2(W[j + 1], co1, ao);
            ao = ffma2(W[j + 2], co2, ao);
            ao = ffma2(W[j + 3], co3, ao);
            ao = ffma2(W[j + 4], co4, ao);
            ao = ffma2(W[j + 5], co5, ao);

            const int goy = oy0 + 2 * (rg * 4 + j); // even, <= 510
            float* pe = o_img + (size_t)goy * OUT_W + gox;
            if (x2ok) {
                if (al8) {
                    *reinterpret_cast<float2*>(pe) = ae;  // 8B-aligned
                } else {
                    pe[0] = ae.x;
                    pe[1] = ae.y;
                }
            } else {
                pe[0] = ae.x;
            }
            if (goy + 1 < OUT_H) {
                float* po = pe + OUT_W;
                po[0] = ao.x;
                if (x2ok) po[1] = ao.y;
            }
        }
    }
}

extern "C" void kernel_launch(void* const* d_in, const int* in_sizes, int n_in,
                              void* d_out, int out_size) {
    const float* x = (const float*)d_in[0];   // [8,64,256,256] f32
    const float* K = (const float*)d_in[1];   // [12,12] f32
    float* out = (float*)d_out;               // [8,64,511,511] f32

    int imgs = in_sizes[0] / (IMG_H * IMG_W); // 512
    dim3 grid((OUT_W + TILE - 1) / TILE,      // 8
              (OUT_H + TILE - 1) / TILE,      // 8
              imgs);                          // 512
    lpf_up2_kernel<<<grid, 256>>>(x, K, out);
}

// round 7
// speedup vs baseline: 1.2000x; 1.2000x over previous
#include <cuda_runtime.h>

// upfirdn2d(up=2, down=1, pad=5), 12x12 separable K = h h^T, via fma.rn.f32x2.
// R3 skeleton (32 regs, occ ~92%): parity-pair outputs, broadcast-input FFMA2,
// sliding register windows in both passes.
// R6: division-free tile-load indexing + LDG.64 interior fast path.

#define IMG_H 256
#define IMG_W 256
#define OUT_H 511
#define OUT_W 511
#define TILE  64
#define IN_T  37      // input rows/cols needed per 64-wide output tile
#define SPITCH 37     // odd pitch -> conflict-free s_in reads
#define TP2   33      // float2 pitch for tmp rows (66 floats)

__device__ __forceinline__ float2 ffma2(float2 a, float2 b, float2 c) {
    float2 d;
    asm("fma.rn.f32x2 %0, %1, %2, %3;"
        : "=l"(*reinterpret_cast<unsigned long long*>(&d))
        : "l"(*reinterpret_cast<unsigned long long*>(&a)),
          "l"(*reinterpret_cast<unsigned long long*>(&b)),
          "l"(*reinterpret_cast<unsigned long long*>(&c)));
    return d;
}

__device__ __forceinline__ float2 fmul2(float2 a, float2 b) {
    float2 d;
    asm("mul.rn.f32x2 %0, %1, %2;"
        : "=l"(*reinterpret_cast<unsigned long long*>(&d))
        : "l"(*reinterpret_cast<unsigned long long*>(&a)),
          "l"(*reinterpret_cast<unsigned long long*>(&b)));
    return d;
}

__device__ __forceinline__ float2 bcast(float w) { return make_float2(w, w); }

__global__ __launch_bounds__(256)
void lpf_up2_kernel(const float* __restrict__ x,
                    const float* __restrict__ K,
                    float* __restrict__ out) {
    __shared__ float  s_in[IN_T * SPITCH];   // input tile (zero-padded halo)
    __shared__ float2 s_tmp[IN_T * TP2];     // horiz result: 37 rows x 64 cols
    __shared__ float2 s_c[6];                // (h_even_tap[t], h_odd_tap[t])

    const int tid = threadIdx.x;
    const int img = blockIdx.z;
    const int ox0 = blockIdx.x * TILE;       // even
    const int oy0 = blockIdx.y * TILE;       // even
    const int mx0 = (ox0 >> 1) - 2;          // even
    const int my0 = (oy0 >> 1) - 2;

    // Recover separable h from K row 5: h[j] = K[5][j] / sqrt(K[5][5]).
    // Sign ambiguity cancels (all taps are h*h products).
    if (tid < 6) {
        float s = rsqrtf(K[5 * 12 + 5]);
        s_c[tid] = make_float2(K[5 * 12 + (10 - 2 * tid)] * s,
                               K[5 * 12 + (11 - 2 * tid)] * s);
    }

    // ---- Load input tile (division-free indexing) ----
    const float* __restrict__ xin = x + (size_t)img * (IMG_H * IMG_W);
    const bool interior =
        (mx0 >= 0) && (mx0 + 38 <= IMG_W) && (my0 >= 0) && (my0 + IN_T <= IMG_H);

    if (interior) {
        // LDG.64 path: 37 rows x 19 float2 = 703 tasks (cols 0..37, col 37 is
        // in-bounds in GMEM and simply not written to smem).
        int r = tid / 19, c = tid - (tid / 19) * 19;     // one const-div only
        #pragma unroll
        for (int it = 0; it < 3; it++) {
            if (r < IN_T) {
                float2 v = *reinterpret_cast<const float2*>(
                    xin + (my0 + r) * IMG_W + mx0 + 2 * c);
                float* dst = s_in + r * SPITCH + 2 * c;
                dst[0] = v.x;
                if (2 * c + 1 < IN_T) dst[1] = v.y;      // skip pad col 37
            }
            r += 13; c += 9;
            if (c >= 19) { c -= 19; r += 1; }
        }
    } else {
        // Scalar path with bounds + zero fill; incremental (r,c) carry.
        int r = tid / IN_T, c = tid - (tid / IN_T) * IN_T;
        #pragma unroll
        for (int it = 0; it < 6; it++) {
            if (r < IN_T) {
                int gy = my0 + r, gx = mx0 + c;
                float v = 0.0f;
                if ((unsigned)gy < IMG_H && (unsigned)gx < IMG_W)
                    v = xin[gy * IMG_W + gx];
                s_in[r * SPITCH + c] = v;
            }
            r += 6; c += 34;
            if (c >= IN_T) { c -= IN_T; r += 1; }
        }
    }
    __syncthreads();

    const float2 c0 = s_c[0], c1 = s_c[1], c2 = s_c[2],
                 c3 = s_c[3], c4 = s_c[4], c5 = s_c[5];

    // ---- Horizontal pass: tmp[r][pair k] = sum_t c[t]*s_in[r][k+t] ----
    // 37 rows x 4 groups of 8 pairs = 148 tasks; broadcast pairs in registers.
    if (tid < IN_T * 4) {
        int kg = tid / IN_T;            // 0..3
        int r  = tid - kg * IN_T;       // 0..36
        int k0 = kg * 8;
        const float* row = s_in + r * SPITCH;
        float2* trow = s_tmp + r * TP2;
        float2 p0 = bcast(row[k0 + 0]), p1 = bcast(row[k0 + 1]),
               p2 = bcast(row[k0 + 2]), p3 = bcast(row[k0 + 3]),
               p4 = bcast(row[k0 + 4]), p5 = bcast(row[k0 + 5]);
        #pragma unroll
        for (int j = 0; j < 8; j++) {
            float2 acc = fmul2(p0, c0);
            acc = ffma2(p1, c1, acc);
            acc = ffma2(p2, c2, acc);
            acc = ffma2(p3, c3, acc);
            acc = ffma2(p4, c4, acc);
            acc = ffma2(p5, c5, acc);
            trow[k0 + j] = acc;
            p0 = p1; p1 = p2; p2 = p3; p3 = p4; p4 = p5;
            if (j < 7) p5 = bcast(row[k0 + j + 6]);   // max col = 36
        }
    }
    __syncthreads();

    // ---- Vertical pass: out rows (2J, 2J+1) = sum_t c[t]*tmp[J+t][ox] ----
    // 64 columns x 4 groups of 8 row-pairs; broadcast pairs in registers.
    const int ox = tid & 63;
    const int j0 = (tid >> 6) * 8;      // 0,8,16,24
    const float* tf = reinterpret_cast<const float*>(s_tmp);  // row stride 66
    float2 v0 = bcast(tf[(j0 + 0) * (TP2 * 2) + ox]);
    float2 v1 = bcast(tf[(j0 + 1) * (TP2 * 2) + ox]);
    float2 v2 = bcast(tf[(j0 + 2) * (TP2 * 2) + ox]);
    float2 v3 = bcast(tf[(j0 + 3) * (TP2 * 2) + ox]);
    float2 v4 = bcast(tf[(j0 + 4) * (TP2 * 2) + ox]);
    float2 v5 = bcast(tf[(j0 + 5) * (TP2 * 2) + ox]);

    float* __restrict__ o_img = out + (size_t)img * ((size_t)OUT_H * OUT_W);
    const int  gox = ox0 + ox;
    const bool xok = (gox < OUT_W);

    #pragma unroll
    for (int j = 0; j < 8; j++) {
        float2 acc = fmul2(v0, c0);
        acc = ffma2(v1, c1, acc);
        acc = ffma2(v2, c2, acc);
        acc = ffma2(v3, c3, acc);
        acc = ffma2(v4, c4, acc);
        acc = ffma2(v5, c5, acc);
        const int goy = oy0 + 2 * (j0 + j);
        if (xok) {
            o_img[(size_t)goy * OUT_W + gox] = acc.x;      // goy <= 510 always
            if (goy + 1 < OUT_H)
                o_img[(size_t)(goy + 1) * OUT_W + gox] = acc.y;
        }
        v0 = v1; v1 = v2; v2 = v3; v3 = v4; v4 = v5;
        if (j < 7) v5 = bcast(tf[(j0 + j + 6) * (TP2 * 2) + ox]); // max row 36
    }
}

extern "C" void kernel_launch(void* const* d_in, const int* in_sizes, int n_in,
                              void* d_out, int out_size) {
    const float* x = (const float*)d_in[0];   // [8,64,256,256] f32
    const float* K = (const float*)d_in[1];   // [12,12] f32
    float* out = (float*)d_out;               // [8,64,511,511] f32

    int imgs = in_sizes[0] / (IMG_H * IMG_W); // 512
    dim3 grid((OUT_W + TILE - 1) / TILE,      // 8
              (OUT_H + TILE - 1) / TILE,      // 8
              imgs);                          // 512
    lpf_up2_kernel<<<grid, 256>>>(x, K, out);
}

// round 8
// speedup vs baseline: 1.2257x; 1.0214x over previous
#include <cuda_runtime.h>

// upfirdn2d(up=2, down=1, pad=5), 12x12 separable K = h h^T, via fma.rn.f32x2.
// R3 skeleton (32 regs, occ ~92%): parity-pair outputs, broadcast-input FFMA2,
// sliding register windows in both passes.
// R7: warp-row tile load -- division-free AND iteration-independent addresses
// (high MLP), block-uniform interior/edge split; constant-offset STG/LDS.

#define IMG_H 256
#define IMG_W 256
#define OUT_H 511
#define OUT_W 511
#define TILE  64
#define IN_T  37      // input rows/cols needed per 64-wide output tile
#define SPITCH 37     // odd pitch -> conflict-free s_in reads
#define TP2   33      // float2 pitch for tmp rows (66 floats)

__device__ __forceinline__ float2 ffma2(float2 a, float2 b, float2 c) {
    float2 d;
    asm("fma.rn.f32x2 %0, %1, %2, %3;"
        : "=l"(*reinterpret_cast<unsigned long long*>(&d))
        : "l"(*reinterpret_cast<unsigned long long*>(&a)),
          "l"(*reinterpret_cast<unsigned long long*>(&b)),
          "l"(*reinterpret_cast<unsigned long long*>(&c)));
    return d;
}

__device__ __forceinline__ float2 fmul2(float2 a, float2 b) {
    float2 d;
    asm("mul.rn.f32x2 %0, %1, %2;"
        : "=l"(*reinterpret_cast<unsigned long long*>(&d))
        : "l"(*reinterpret_cast<unsigned long long*>(&a)),
          "l"(*reinterpret_cast<unsigned long long*>(&b)));
    return d;
}

__device__ __forceinline__ float2 bcast(float w) { return make_float2(w, w); }

__global__ __launch_bounds__(256)
void lpf_up2_kernel(const float* __restrict__ x,
                    const float* __restrict__ K,
                    float* __restrict__ out) {
    __shared__ float  s_in[IN_T * SPITCH];   // input tile (zero-padded halo)
    __shared__ float2 s_tmp[IN_T * TP2];     // horiz result: 37 rows x 64 cols
    __shared__ float2 s_c[6];                // (h_even_tap[t], h_odd_tap[t])

    const int tid = threadIdx.x;
    const int img = blockIdx.z;
    const int ox0 = blockIdx.x * TILE;       // even
    const int oy0 = blockIdx.y * TILE;       // even
    const int mx0 = (ox0 >> 1) - 2;
    const int my0 = (oy0 >> 1) - 2;

    // Recover separable h from K row 5: h[j] = K[5][j] / sqrt(K[5][5]).
    // Sign ambiguity cancels (all taps are h*h products).
    if (tid < 6) {
        float s = rsqrtf(K[5 * 12 + 5]);
        s_c[tid] = make_float2(K[5 * 12 + (10 - 2 * tid)] * s,
                               K[5 * 12 + (11 - 2 * tid)] * s);
    }

    // ---- Load input tile: warp w handles rows w, w+8, ..., lane covers col
    // lane, lanes 0..4 also cover cols 32..36. No divisions; every iteration's
    // address is independent -> LDGs batch (high MLP).
    const float* __restrict__ xin = x + (size_t)img * (IMG_H * IMG_W);
    {
        const int w    = tid >> 5;
        const int lane = tid & 31;
        const bool interior = (mx0 >= 0) && (mx0 + IN_T <= IMG_W) &&
                              (my0 >= 0) && (my0 + IN_T <= IMG_H);
        if (interior) {
            #pragma unroll
            for (int i = 0; i < 5; i++) {
                int r = w + 8 * i;
                if (r < IN_T) {
                    const float* src = xin + (my0 + r) * IMG_W + mx0;
                    float* dst = s_in + r * SPITCH;
                    dst[lane] = src[lane];
                    if (lane < IN_T - 32) dst[32 + lane] = src[32 + lane];
                }
            }
        } else {
            #pragma unroll
            for (int i = 0; i < 5; i++) {
                int r = w + 8 * i;
                if (r < IN_T) {
                    int gy = my0 + r;
                    bool yok = (unsigned)gy < IMG_H;
                    const float* src = xin + gy * IMG_W + mx0;
                    float* dst = s_in + r * SPITCH;
                    int gx0 = mx0 + lane;
                    float v0 = (yok && (unsigned)gx0 < IMG_W) ? src[lane] : 0.0f;
                    dst[lane] = v0;
                    if (lane < IN_T - 32) {
                        int gx1 = gx0 + 32;
                        float v1 = (yok && (unsigned)gx1 < IMG_W) ? src[32 + lane] : 0.0f;
                        dst[32 + lane] = v1;
                    }
                }
            }
        }
    }
    __syncthreads();

    const float2 c0 = s_c[0], c1 = s_c[1], c2 = s_c[2],
                 c3 = s_c[3], c4 = s_c[4], c5 = s_c[5];

    // ---- Horizontal pass: tmp[r][pair k] = sum_t c[t]*s_in[r][k+t] ----
    // 37 rows x 4 groups of 8 pairs = 148 tasks; broadcast pairs in registers.
    if (tid < IN_T * 4) {
        int kg = tid / IN_T;            // 0..3
        int r  = tid - kg * IN_T;       // 0..36
        int k0 = kg * 8;
        const float* row = s_in + r * SPITCH + k0;
        float2* trow = s_tmp + r * TP2 + k0;
        float2 p0 = bcast(row[0]), p1 = bcast(row[1]),
               p2 = bcast(row[2]), p3 = bcast(row[3]),
               p4 = bcast(row[4]), p5 = bcast(row[5]);
        #pragma unroll
        for (int j = 0; j < 8; j++) {
            float2 acc = fmul2(p0, c0);
            acc = ffma2(p1, c1, acc);
            acc = ffma2(p2, c2, acc);
            acc = ffma2(p3, c3, acc);
            acc = ffma2(p4, c4, acc);
            acc = ffma2(p5, c5, acc);
            trow[j] = acc;
            p0 = p1; p1 = p2; p2 = p3; p3 = p4; p4 = p5;
            if (j < 7) p5 = bcast(row[j + 6]);        // max col = 36
        }
    }
    __syncthreads();

    // ---- Vertical pass: out rows (2J, 2J+1) = sum_t c[t]*tmp[J+t][ox] ----
    // 64 columns x 4 groups of 8 row-pairs; broadcast pairs in registers.
    const int ox = tid & 63;
    const int j0 = (tid >> 6) * 8;      // 0,8,16,24
    const float* tcol = reinterpret_cast<const float*>(s_tmp) + j0 * (TP2 * 2) + ox;
    float2 v0 = bcast(tcol[0 * (TP2 * 2)]);
    float2 v1 = bcast(tcol[1 * (TP2 * 2)]);
    float2 v2 = bcast(tcol[2 * (TP2 * 2)]);
    float2 v3 = bcast(tcol[3 * (TP2 * 2)]);
    float2 v4 = bcast(tcol[4 * (TP2 * 2)]);
    float2 v5 = bcast(tcol[5 * (TP2 * 2)]);

    const int  gox = ox0 + ox;
    const bool xok = (gox < OUT_W);
    // Base pointer for this thread's first output row; per-j offsets constant.
    float* __restrict__ p0 =
        out + (size_t)img * ((size_t)OUT_H * OUT_W) +
        (size_t)(oy0 + 2 * j0) * OUT_W + gox;
    const bool lastrow = (oy0 + 2 * j0 + 15 > OUT_H - 1);  // only oy0=448,j0=24

    #pragma unroll
    for (int j = 0; j < 8; j++) {
        float2 acc = fmul2(v0, c0);
        acc = ffma2(v1, c1, acc);
        acc = ffma2(v2, c2, acc);
        acc = ffma2(v3, c3, acc);
        acc = ffma2(v4, c4, acc);
        acc = ffma2(v5, c5, acc);
        if (xok) {
            p0[(size_t)(2 * j) * OUT_W] = acc.x;           // even row, always in
            if (!lastrow || j < 7)                          // odd row 511 skipped
                p0[(size_t)(2 * j + 1) * OUT_W] = acc.y;
        }
        v0 = v1; v1 = v2; v2 = v3; v3 = v4; v4 = v5;
        if (j < 7) v5 = bcast(tcol[(j + 6) * (TP2 * 2)]);  // max row 36
    }
}

extern "C" void kernel_launch(void* const* d_in, const int* in_sizes, int n_in,
                              void* d_out, int out_size) {
    const float* x = (const float*)d_in[0];   // [8,64,256,256] f32
    const float* K = (const float*)d_in[1];   // [12,12] f32
    float* out = (float*)d_out;               // [8,64,511,511] f32

    int imgs = in_sizes[0] / (IMG_H * IMG_W); // 512
    dim3 grid((OUT_W + TILE - 1) / TILE,      // 8
              (OUT_H + TILE - 1) / TILE,      // 8
              imgs);                          // 512
    lpf_up2_kernel<<<grid, 256>>>(x, K, out);
}

// round 9
// speedup vs baseline: 1.4777x; 1.2056x over previous
#include <cuda_runtime.h>

// upfirdn2d(up=2, down=1, pad=5), 12x12 separable K = h h^T, via fma.rn.f32x2.
// R3 skeleton (proven 125us): parity-pair outputs, broadcast-input FFMA2,
// sliding register windows, simple idx-based load loop (high MLP).
// R8: 128-wide x 64-tall output tile -> halo 1.337 -> 1.247, half the blocks,
// better-coalesced 69-float rows. Structure otherwise identical to R3.

#define IMG_H 256
#define IMG_W 256
#define OUT_H 511
#define OUT_W 511
#define TILE_W 128
#define TILE_H 64
#define IN_W  69      // input cols per 128-wide output tile
#define IN_H  37      // input rows per 64-tall output tile
#define SPITCH 69     // stride mod 32 = 5 -> conflict-free s_in column reads
#define TP2   65      // float2 pitch for tmp rows (130 floats)

__device__ __forceinline__ float2 ffma2(float2 a, float2 b, float2 c) {
    float2 d;
    asm("fma.rn.f32x2 %0, %1, %2, %3;"
        : "=l"(*reinterpret_cast<unsigned long long*>(&d))
        : "l"(*reinterpret_cast<unsigned long long*>(&a)),
          "l"(*reinterpret_cast<unsigned long long*>(&b)),
          "l"(*reinterpret_cast<unsigned long long*>(&c)));
    return d;
}

__device__ __forceinline__ float2 fmul2(float2 a, float2 b) {
    float2 d;
    asm("mul.rn.f32x2 %0, %1, %2;"
        : "=l"(*reinterpret_cast<unsigned long long*>(&d))
        : "l"(*reinterpret_cast<unsigned long long*>(&a)),
          "l"(*reinterpret_cast<unsigned long long*>(&b)));
    return d;
}

__device__ __forceinline__ float2 bcast(float w) { return make_float2(w, w); }

__global__ __launch_bounds__(256)
void lpf_up2_kernel(const float* __restrict__ x,
                    const float* __restrict__ K,
                    float* __restrict__ out) {
    __shared__ float  s_in[IN_H * SPITCH];   // 37 x 69 input tile (zero-padded)
    __shared__ float2 s_tmp[IN_H * TP2];     // horiz result: 37 rows x 128 cols
    __shared__ float2 s_c[6];                // (h_even_tap[t], h_odd_tap[t])

    const int tid = threadIdx.x;
    const int img = blockIdx.z;
    const int ox0 = blockIdx.x * TILE_W;     // even
    const int oy0 = blockIdx.y * TILE_H;     // even
    const int mx0 = (ox0 >> 1) - 2;
    const int my0 = (oy0 >> 1) - 2;

    // Recover separable h from K row 5: h[j] = K[5][j] / sqrt(K[5][5]).
    // Sign ambiguity cancels (all taps are h*h products).
    if (tid < 6) {
        float s = rsqrtf(K[5 * 12 + 5]);
        s_c[tid] = make_float2(K[5 * 12 + (10 - 2 * tid)] * s,
                               K[5 * 12 + (11 - 2 * tid)] * s);
    }

    // ---- Load input tile (R3-style: independent iterations, high MLP) ----
    const float* __restrict__ xin = x + (size_t)img * (IMG_H * IMG_W);
    #pragma unroll
    for (int idx = tid; idx < IN_H * IN_W; idx += 256) {
        int r = idx / IN_W;
        int c = idx - r * IN_W;
        int gy = my0 + r;
        int gx = mx0 + c;
        float v = 0.0f;
        if ((unsigned)gy < IMG_H && (unsigned)gx < IMG_W)
            v = xin[gy * IMG_W + gx];
        s_in[r * SPITCH + c] = v;
    }
    __syncthreads();

    const float2 c0 = s_c[0], c1 = s_c[1], c2 = s_c[2],
                 c3 = s_c[3], c4 = s_c[4], c5 = s_c[5];

    // ---- Horizontal pass: tmp[r][pair k] = sum_t c[t]*s_in[r][k+t] ----
    // 37 rows x 8 groups of 8 pairs = 296 tasks; two task slots per thread.
    #pragma unroll
    for (int tt = 0; tt < 2; tt++) {
        int t = tid + 256 * tt;
        if (t < IN_H * 8) {
            int kg = t / IN_H;            // 0..7
            int r  = t - kg * IN_H;       // 0..36
            int k0 = kg * 8;
            const float* row = s_in + r * SPITCH + k0;
            float2* trow = s_tmp + r * TP2 + k0;
            float2 p0 = bcast(row[0]), p1 = bcast(row[1]),
                   p2 = bcast(row[2]), p3 = bcast(row[3]),
                   p4 = bcast(row[4]), p5 = bcast(row[5]);
            #pragma unroll
            for (int j = 0; j < 8; j++) {
                float2 acc = fmul2(p0, c0);
                acc = ffma2(p1, c1, acc);
                acc = ffma2(p2, c2, acc);
                acc = ffma2(p3, c3, acc);
                acc = ffma2(p4, c4, acc);
                acc = ffma2(p5, c5, acc);
                trow[j] = acc;
                p0 = p1; p1 = p2; p2 = p3; p3 = p4; p4 = p5;
                if (j < 7) p5 = bcast(row[j + 6]);   // max col = 56+7+6 = 68
            }
        }
    }
    __syncthreads();

    // ---- Vertical pass: out rows (2J, 2J+1) = sum_t c[t]*tmp[J+t][ox] ----
    // 128 columns x 2 groups of 16 row-pairs; broadcast pairs in registers.
    const int ox = tid & 127;
    const int j0 = (tid >> 7) * 16;     // 0 or 16
    const float* tcol = reinterpret_cast<const float*>(s_tmp) + j0 * (TP2 * 2) + ox;
    float2 v0 = bcast(tcol[0 * (TP2 * 2)]);
    float2 v1 = bcast(tcol[1 * (TP2 * 2)]);
    float2 v2 = bcast(tcol[2 * (TP2 * 2)]);
    float2 v3 = bcast(tcol[3 * (TP2 * 2)]);
    float2 v4 = bcast(tcol[4 * (TP2 * 2)]);
    float2 v5 = bcast(tcol[5 * (TP2 * 2)]);

    float* __restrict__ o_img = out + (size_t)img * ((size_t)OUT_H * OUT_W);
    const int  gox = ox0 + ox;
    const bool xok = (gox < OUT_W);

    #pragma unroll
    for (int j = 0; j < 16; j++) {
        float2 acc = fmul2(v0, c0);
        acc = ffma2(v1, c1, acc);
        acc = ffma2(v2, c2, acc);
        acc = ffma2(v3, c3, acc);
        acc = ffma2(v4, c4, acc);
        acc = ffma2(v5, c5, acc);
        const int goy = oy0 + 2 * (j0 + j);
        if (xok) {
            o_img[(size_t)goy * OUT_W + gox] = acc.x;      // goy <= 510 always
            if (goy + 1 < OUT_H)
                o_img[(size_t)(goy + 1) * OUT_W + gox] = acc.y;
        }
        v0 = v1; v1 = v2; v2 = v3; v3 = v4; v4 = v5;
        if (j < 15) v5 = bcast(tcol[(j + 6) * (TP2 * 2)]); // max row 16+14+6=36
    }
}

extern "C" void kernel_launch(void* const* d_in, const int* in_sizes, int n_in,
                              void* d_out, int out_size) {
    const float* x = (const float*)d_in[0];   // [8,64,256,256] f32
    const float* K = (const float*)d_in[1];   // [12,12] f32
    float* out = (float*)d_out;               // [8,64,511,511] f32

    int imgs = in_sizes[0] / (IMG_H * IMG_W); // 512
    dim3 grid((OUT_W + TILE_W - 1) / TILE_W,  // 4
              (OUT_H + TILE_H - 1) / TILE_H,  // 8
              imgs);                          // 512
    lpf_up2_kernel<<<grid, 256>>>(x, K, out);
}